// round 4
// baseline (speedup 1.0000x reference)
#include <cuda_runtime.h>
#include <math.h>

#define Bsz 4096
#define Tsz 64
#define Fsz 37
#define TB 8          // batch elements per CTA
#define NP 24         // TB * 3 timesteps
#define NT 256        // threads: (gate-pair g2, hidden unit j)
#define FDIM 150      // lin width
#define GATES 512
#define H 128

typedef unsigned long long ull;

// shared memory layout (floats)
#define OFF_FEAT 0        // 24*37 = 888  (aliased by head buffers later)
#define OFF_T1M1 888      // 24*16 = 384
#define OFF_S1   1272     // 24*32 = 768
#define OFF_LIN  2040     // 3*150*8 = 3600 (byte 8160, 32B aligned)
#define OFF_H    5640     // 128*8 = 1024   (byte 22560, 32B aligned)
#define OFF_Z    6664     // 4*128*8 = 4096 (byte 26656, 32B aligned)
#define SMEM_FLOATS 10760 // 43040 bytes < 48KB static limit

struct Params {
    const float *feature;
    const float *w_m1, *b_m1, *w_m2, *b_m2;
    const float *w_t1, *b_t1, *w_t2, *b_t2;
    const float *w_s1, *b_s1, *w_s2, *b_s2;
    const float *w_lk, *w_lr, *b_l;
    const float *w_p1, *b_p1, *w_p2, *b_p2, *w_p3, *b_p3, *w_p4, *b_p4, *w_p5, *b_p5;
    float *out;
};

__device__ __forceinline__ float lrelu(float x) { return x >= 0.f ? x : 0.2f * x; }
__device__ __forceinline__ float sigm(float x) { return 1.f / (1.f + __expf(-x)); }

__device__ __forceinline__ ull pack2(float lo, float hi) {
    ull v;
    asm("mov.b64 %0, {%1, %2};" : "=l"(v) : "f"(lo), "f"(hi));
    return v;
}
__device__ __forceinline__ void ffma2(ull &acc, ull a, ull b) {
    asm("fma.rn.f32x2 %0, %1, %2, %0;" : "+l"(acc) : "l"(a), "l"(b));
}

// lin transposed: [t][f][b], b contiguous (8 floats = 32B per row)
#define LIDX(t, f, b) (((t) * FDIM + (f)) * TB + (b))

__global__ void __launch_bounds__(NT) lstm_fused_kernel(Params P) {
    __shared__ __align__(32) float sm[SMEM_FLOATS];
    const int tid = threadIdx.x;
    const int bg0 = blockIdx.x * TB;

    float *feat = sm + OFF_FEAT;
    float *t1m1 = sm + OFF_T1M1;
    float *S1   = sm + OFF_S1;
    float *linT = sm + OFF_LIN;
    float *hT   = sm + OFF_H;
    float *zbuf = sm + OFF_Z;

    // ---- load feature rows t=0..2 for 8 batch elems ----
    for (int i = tid; i < NP * Fsz; i += NT) {
        int p = i / Fsz, f = i % Fsz;
        int b = p / 3, t = p % 3;
        feat[p * Fsz + f] =
            P.feature[(size_t)(bg0 + b) * Tsz * Fsz + (size_t)t * Fsz + f];
    }
    __syncthreads();

    // ---- pass1: M1 (q<8) and T1 (q>=8), per (b,t) pair p ----
    for (int i = tid; i < NP * 16; i += NT) {
        int p = i >> 4, q = i & 15;
        const float *fr = feat + p * Fsz;
        float acc;
        if (q < 8) {
            acc = P.b_m1[q];
            #pragma unroll
            for (int f = 0; f < 3; ++f) acc += fr[33 + f] * P.w_m1[f * 8 + q];
            acc = lrelu(acc);
        } else {
            int j = q - 8;
            acc = P.b_t1[j];
            #pragma unroll
            for (int f = 0; f < Fsz; ++f) acc += fr[f] * P.w_t1[f * 8 + j];
            acc = lrelu(acc);
            acc = fabsf(acc);
        }
        t1m1[i] = acc;
    }
    __syncthreads();

    // ---- pass2: M -> lin[0:16], Tsk -> lin[16:32], Psk -> lin[32:48] ----
    for (int i = tid; i < NP * 32; i += NT) {
        int p = i >> 5, q = i & 31;
        int b = p / 3, t = p % 3;
        if (q < 16) {
            float acc = P.b_m2[q];
            #pragma unroll
            for (int k = 0; k < 8; ++k) acc += t1m1[p * 16 + k] * P.w_m2[k * 16 + q];
            linT[LIDX(t, q, b)] = lrelu(acc);
        } else {
            int j = q - 16;
            float acc = P.b_t2[j];
            #pragma unroll
            for (int k = 0; k < 8; ++k) acc += t1m1[p * 16 + 8 + k] * P.w_t2[k * 16 + j];
            float v = (acc >= 0.f) ? acc : -0.2f * acc;  // abs(lrelu)
            linT[LIDX(t, 16 + j, b)] = v;
            linT[LIDX(t, 32 + j, b)] = log1pf(v);
        }
    }
    // Pa -> lin[48], feature copy -> lin[113:150]
    for (int i = tid; i < NP * 38; i += NT) {
        int p = i / 38, q = i % 38;
        int b = p / 3, t = p % 3;
        if (q == 0) linT[LIDX(t, 48, b)] = log1pf(feat[p * Fsz + 31]);
        else        linT[LIDX(t, 113 + (q - 1), b)] = feat[p * Fsz + (q - 1)];
    }
    __syncthreads();

    // ---- pass3: S1 = lrelu(s_in @ w_s1 + b_s1) ----
    for (int i = tid; i < NP * 32; i += NT) {
        int p = i >> 5, j = i & 31;
        int b = p / 3, t = p % 3;
        float acc = P.b_s1[j];
        for (int f = 0; f < 49; ++f) acc += linT[LIDX(t, f, b)] * P.w_s1[f * 32 + j];
        const float *fr = feat + p * Fsz;
        #pragma unroll
        for (int e = 0; e < 6; ++e) acc += fr[27 + e] * P.w_s1[(49 + e) * 32 + j];
        #pragma unroll
        for (int e = 0; e < 3; ++e) acc += fr[33 + e] * P.w_s1[(55 + e) * 32 + j];
        S1[p * 32 + j] = lrelu(acc);
    }
    __syncthreads();

    // ---- pass4: S -> lin[49:113] ----
    for (int i = tid; i < NP * 64; i += NT) {
        int p = i >> 6, j = i & 63;
        int b = p / 3, t = p % 3;
        float acc = P.b_s2[j];
        #pragma unroll
        for (int k = 0; k < 32; ++k) acc += S1[p * 32 + k] * P.w_s2[k * 64 + j];
        linT[LIDX(t, 49 + j, b)] = lrelu(acc);
    }
    __syncthreads();

    // ---- LSTM: 3 timesteps. Thread (g2, j): g2 = tid>>7 selects gate pair
    // ({i,f} or {g,o}) of hidden unit j = tid&127. Batches packed in f32x2
    // lanes; z exchanged through zbuf once per step; c-state lives in the
    // registers of the g2==0 threads.
    {
        const int j = tid & (H - 1);
        const int g2 = tid >> 7;              // 0: gates i,f   1: gates g,o
        const float *wk = P.w_lk + j + g2 * 2 * H;
        const float *wr = P.w_lr + j + g2 * 2 * H;
        ull bia[2];
        #pragma unroll
        for (int cc = 0; cc < 2; ++cc) {
            float bv = P.b_l[j + (2 * g2 + cc) * H];
            bia[cc] = pack2(bv, bv);
        }
        float cres[TB];
        #pragma unroll
        for (int b = 0; b < TB; ++b) cres[b] = 0.f;

        for (int t = 0; t < 3; ++t) {
            ull acc[2][4];
            #pragma unroll
            for (int cc = 0; cc < 2; ++cc)
                #pragma unroll
                for (int p = 0; p < 4; ++p) acc[cc][p] = bia[cc];

            // input GEMM: z += lin_t @ w_lk
            #pragma unroll 4
            for (int f = 0; f < FDIM; ++f) {
                const ulonglong2 *lp =
                    (const ulonglong2 *)(linT + (t * FDIM + f) * TB);
                ulonglong2 u0 = lp[0];
                ulonglong2 u1 = lp[1];
                #pragma unroll
                for (int cc = 0; cc < 2; ++cc) {
                    float w = __ldg(wk + f * GATES + cc * H);
                    ull wd = pack2(w, w);
                    ffma2(acc[cc][0], u0.x, wd);
                    ffma2(acc[cc][1], u0.y, wd);
                    ffma2(acc[cc][2], u1.x, wd);
                    ffma2(acc[cc][3], u1.y, wd);
                }
            }
            // recurrent GEMM: z += h @ w_lr  (h == 0 at t=0)
            if (t > 0) {
                #pragma unroll 4
                for (int f = 0; f < H; ++f) {
                    const ulonglong2 *hp = (const ulonglong2 *)(hT + f * TB);
                    ulonglong2 u0 = hp[0];
                    ulonglong2 u1 = hp[1];
                    #pragma unroll
                    for (int cc = 0; cc < 2; ++cc) {
                        float w = __ldg(wr + f * GATES + cc * H);
                        ull wd = pack2(w, w);
                        ffma2(acc[cc][0], u0.x, wd);
                        ffma2(acc[cc][1], u0.y, wd);
                        ffma2(acc[cc][2], u1.x, wd);
                        ffma2(acc[cc][3], u1.y, wd);
                    }
                }
            }

            // publish z for both gate pairs; hT reads for this t are done
            __syncthreads();
            #pragma unroll
            for (int cc = 0; cc < 2; ++cc) {
                ulonglong2 *zrow =
                    (ulonglong2 *)(zbuf + ((2 * g2 + cc) * H + j) * TB);
                zrow[0] = make_ulonglong2(acc[cc][0], acc[cc][1]);
                zrow[1] = make_ulonglong2(acc[cc][2], acc[cc][3]);
            }
            __syncthreads();

            // gate nonlinearity + state update (g2==0 threads own unit j)
            if (g2 == 0) {
                const float *zi = zbuf + (0 * H + j) * TB;
                const float *zf = zbuf + (1 * H + j) * TB;
                const float *zg = zbuf + (2 * H + j) * TB;
                const float *zo = zbuf + (3 * H + j) * TB;
                float hv[TB];
                #pragma unroll
                for (int b = 0; b < TB; ++b) {
                    float cv = sigm(zf[b]) * cres[b] + sigm(zi[b]) * lrelu(zg[b]);
                    cres[b] = cv;
                    hv[b] = sigm(zo[b]) * lrelu(cv);
                }
                float4 *hrow = (float4 *)(hT + j * TB);
                hrow[0] = make_float4(hv[0], hv[1], hv[2], hv[3]);
                hrow[1] = make_float4(hv[4], hv[5], hv[6], hv[7]);
            }
            __syncthreads();
        }
    }

    // ---- head at t=2 (buffers alias dead front-end smem) ----
    float *d1 = sm;        // 8*64
    float *d2 = sm + 512;  // 8*32
    float *d3 = sm + 768;  // 8*16
    float *d4 = sm + 896;  // 8*8
    float *d5 = sm + 960;  // 8*3

    for (int i = tid; i < TB * 64; i += NT) {
        int b = i >> 6, j = i & 63;
        float acc = P.b_p1[j];
        for (int k = 0; k < H; ++k) acc += hT[k * TB + b] * P.w_p1[k * 64 + j];
        d1[i] = lrelu(acc);
    }
    __syncthreads();
    for (int i = tid; i < TB * 32; i += NT) {
        int b = i >> 5, j = i & 31;
        float acc = P.b_p2[j];
        #pragma unroll
        for (int k = 0; k < 64; ++k) acc += d1[b * 64 + k] * P.w_p2[k * 32 + j];
        d2[i] = lrelu(acc);
    }
    __syncthreads();
    for (int i = tid; i < TB * 16; i += NT) {
        int b = i >> 4, j = i & 15;
        float acc = P.b_p3[j];
        #pragma unroll
        for (int k = 0; k < 32; ++k) acc += d2[b * 32 + k] * P.w_p3[k * 16 + j];
        d3[i] = lrelu(acc);
    }
    __syncthreads();
    for (int i = tid; i < TB * 8; i += NT) {
        int b = i >> 3, j = i & 7;
        float acc = P.b_p4[j];
        #pragma unroll
        for (int k = 0; k < 16; ++k) acc += d3[b * 16 + k] * P.w_p4[k * 8 + j];
        d4[i] = lrelu(acc);
    }
    __syncthreads();
    for (int i = tid; i < TB * 3; i += NT) {
        int b = i / 3, j = i % 3;
        float acc = P.b_p5[j];
        #pragma unroll
        for (int k = 0; k < 8; ++k) acc += d4[b * 8 + k] * P.w_p5[k * 3 + j];
        d5[i] = lrelu(acc);
    }
    __syncthreads();

    // ---- softmax + write both outputs ----
    if (tid < TB) {
        int b = tid;
        float l0 = d5[b * 3 + 0], l1 = d5[b * 3 + 1], l2 = d5[b * 3 + 2];
        float m = fmaxf(l0, fmaxf(l1, l2));
        float e0 = __expf(l0 - m), e1 = __expf(l1 - m), e2 = __expf(l2 - m);
        float inv = 1.f / (e0 + e1 + e2);
        float o0 = e0 * inv, o1 = e1 * inv, o2 = e2 * inv;
        size_t gb = (size_t)(bg0 + b);
        float *outp = P.out + gb * 3;
        outp[0] = o0; outp[1] = o1; outp[2] = o2;
        float *xp = P.out + (size_t)Bsz * 3 + gb * 13;
        const float *fsrc = P.feature + gb * Tsz * Fsz + 2 * Fsz + 27;
        #pragma unroll
        for (int q = 0; q < 10; ++q) xp[q] = fsrc[q];
        xp[10] = o0; xp[11] = o1; xp[12] = o2;
    }
}

extern "C" void kernel_launch(void *const *d_in, const int *in_sizes, int n_in,
                              void *d_out, int out_size) {
    Params P;
    P.feature = (const float *)d_in[0];
    P.w_m1 = (const float *)d_in[1];  P.b_m1 = (const float *)d_in[2];
    P.w_m2 = (const float *)d_in[3];  P.b_m2 = (const float *)d_in[4];
    P.w_t1 = (const float *)d_in[5];  P.b_t1 = (const float *)d_in[6];
    P.w_t2 = (const float *)d_in[7];  P.b_t2 = (const float *)d_in[8];
    P.w_s1 = (const float *)d_in[9];  P.b_s1 = (const float *)d_in[10];
    P.w_s2 = (const float *)d_in[11]; P.b_s2 = (const float *)d_in[12];
    P.w_lk = (const float *)d_in[13];
    P.w_lr = (const float *)d_in[14];
    P.b_l  = (const float *)d_in[15];
    P.w_p1 = (const float *)d_in[16]; P.b_p1 = (const float *)d_in[17];
    P.w_p2 = (const float *)d_in[18]; P.b_p2 = (const float *)d_in[19];
    P.w_p3 = (const float *)d_in[20]; P.b_p3 = (const float *)d_in[21];
    P.w_p4 = (const float *)d_in[22]; P.b_p4 = (const float *)d_in[23];
    P.w_p5 = (const float *)d_in[24]; P.b_p5 = (const float *)d_in[25];
    P.out = (float *)d_out;

    lstm_fused_kernel<<<Bsz / TB, NT>>>(P);
}